// round 10
// baseline (speedup 1.0000x reference)
#include <cuda_runtime.h>

#define IMG_W 200
#define CHAN 512
#define NF4  (CHAN / 4)       // 128 float4 per pixel
#define POOL 7
#define NROI 300

// grid = (4, 300): blockIdx.x = channel quarter q, blockIdx.y = roi.
// 224 threads = 7 warps; warp w handles pool row gy = w, sweeping gx = 0..6.
// Each block touches only a 128-channel (512B/pixel) slice of its ROI's
// ~150 distinct corner pixels -> ~77KB working set, fits L1. Corner pixels
// repeated across the 7x7 grid (always when w<8 or h<8) hit L1 instead of L2.
__global__ void __launch_bounds__(224) roi_pool_cq_kernel(
    const float* __restrict__ img,   // [200,200,512]
    const int*   __restrict__ rois,  // [300,4] = (x,y,w,h)
    float*       __restrict__ out)   // [300,7,7,512]
{
    const int q    = blockIdx.x;              // channel quarter 0..3
    const int roi  = blockIdx.y;
    const int gy   = threadIdx.x >> 5;        // warp id 0..6
    const int lane = threadIdx.x & 31;

    const int4 r = __ldg((const int4*)rois + roi);
    const int x0 = r.x, y0 = r.y, w = r.z, h = r.w;

    // y-setup once per warp (reference numerics).
    const float ys = (float)y0 + (float)gy * ((float)h / (float)POOL);
    const int   ty = (int)floorf(ys);
    const float fy = ys - (float)ty;
    const int   by = min(ty + 1, y0 + h - 1);
    const bool  ly = (fy != 0.0f);
    const float omfy = 1.0f - fy;

    const int rowt = ty * IMG_W;
    const int rowb = by * IMG_W;
    const float w7 = (float)w / (float)POOL;
    const int xmax = x0 + w - 1;

    // per-thread channel offset within pixel (float4 units)
    const int coff = q * 32 + lane;

    const float4* __restrict__ base = (const float4*)img;
    float4* __restrict__ out4 = (float4*)out;
    const int obase = (roi * (POOL * POOL) + gy * POOL) * NF4 + coff;

    const float4 zero = make_float4(0.f, 0.f, 0.f, 0.f);

    #pragma unroll
    for (int gx = 0; gx < POOL; gx++) {
        const float xs = (float)x0 + (float)gx * w7;
        const int   tx = (int)floorf(xs);
        const float fx = xs - (float)tx;
        const int   bx = min(tx + 1, xmax);
        const bool  lx = (fx != 0.0f);

        const float4 v00 = __ldg(base + (rowt + tx) * NF4 + coff);
        float4 v01 = zero, v10 = zero, v11 = zero;
        if (lx)       v01 = __ldg(base + (rowt + bx) * NF4 + coff);
        if (ly)       v10 = __ldg(base + (rowb + tx) * NF4 + coff);
        if (lx && ly) v11 = __ldg(base + (rowb + bx) * NF4 + coff);

        const float omfx = 1.0f - fx;

        float4 res;
        res.x = omfy * (omfx * v00.x + fx * v01.x) + fy * (omfx * v10.x + fx * v11.x);
        res.y = omfy * (omfx * v00.y + fx * v01.y) + fy * (omfx * v10.y + fx * v11.y);
        res.z = omfy * (omfx * v00.z + fx * v01.z) + fy * (omfx * v10.z + fx * v11.z);
        res.w = omfy * (omfx * v00.w + fx * v01.w) + fy * (omfx * v10.w + fx * v11.w);

        out4[obase + gx * NF4] = res;
    }
}

extern "C" void kernel_launch(void* const* d_in, const int* in_sizes, int n_in,
                              void* d_out, int out_size) {
    const float* img  = (const float*)d_in[0];
    const int*   rois = (const int*)d_in[1];
    float*       out  = (float*)d_out;

    dim3 grid(4, NROI);   // (channel quarter, roi) = 1200 blocks
    roi_pool_cq_kernel<<<grid, 224>>>(img, rois, out);
}